// round 14
// baseline (speedup 1.0000x reference)
#include <cuda_runtime.h>

// Polar decomposition of A = rotation[n] @ mat. One warp per CTA (TPB=32,
// no __syncthreads -> per-warp early retirement).
// 2 matrices/thread packed f32x2.
//  head: 4 det-scaled Newton steps (g=|det|^(-1/3), bit trick + 1 FMA polish)
//        - unrolled, zero votes (no Ginibre input converges in <4 steps).
//  tail: plain Newton X <- 0.5*X + (0.5/det)*cof(X) with PRE-step exit test:
//        det is computed before the update anyway, so when ||det|-1| < 2e-4
//        for the whole warp we exit WITHOUT the final apply (saves the
//        guaranteed-wasted polish step R13 always performed).

#define TPB 32
typedef unsigned long long u64;

__device__ __forceinline__ u64 f2pack(float lo, float hi) {
    u64 r; asm("mov.b64 %0, {%1, %2};" : "=l"(r) : "f"(lo), "f"(hi)); return r;
}
__device__ __forceinline__ void f2unpack(u64 v, float& lo, float& hi) {
    asm("mov.b64 {%0, %1}, %2;" : "=f"(lo), "=f"(hi) : "l"(v));
}
__device__ __forceinline__ u64 f2mul(u64 a, u64 b) {
    u64 d; asm("mul.rn.f32x2 %0, %1, %2;" : "=l"(d) : "l"(a), "l"(b)); return d;
}
__device__ __forceinline__ u64 f2fma(u64 a, u64 b, u64 c) {
    u64 d; asm("fma.rn.f32x2 %0, %1, %2, %3;" : "=l"(d) : "l"(a), "l"(b), "l"(c)); return d;
}
__device__ __forceinline__ u64 f2neg(u64 a) { return a ^ 0x8000000080000000ULL; }
__device__ __forceinline__ float rcp_fast(float x) {
    float r; asm("rcp.approx.f32 %0, %1;" : "=f"(r) : "f"(x)); return r;
}

// |x|^(-1/3): bit trick + 1 FMA polish (~2e-3, fine for preconditioning).
__device__ __forceinline__ float invcbrt1(float x) {
    int i = __float_as_int(x);
    i = 0x54A2FA8C - i / 3;
    float y = __int_as_float(i);
    const float y3 = y * y * y;
    return y * 0.33333333f * fmaf(-x, y3, 4.0f);
}

struct P2 { u64 x0,x1,x2,x3,x4,x5,x6,x7,x8; };

__device__ __forceinline__ void cof_det(const P2& X, u64 C[9], u64& det) {
    const u64 n0 = f2neg(X.x0), n1 = f2neg(X.x1), n2 = f2neg(X.x2);
    const u64 n3 = f2neg(X.x3), n4 = f2neg(X.x4), n5 = f2neg(X.x5);
    C[0] = f2fma(X.x4, X.x8, f2mul(n5, X.x7));
    C[1] = f2fma(X.x5, X.x6, f2mul(n3, X.x8));
    C[2] = f2fma(X.x3, X.x7, f2mul(n4, X.x6));
    C[3] = f2fma(X.x2, X.x7, f2mul(n1, X.x8));
    C[4] = f2fma(X.x0, X.x8, f2mul(n2, X.x6));
    C[5] = f2fma(X.x1, X.x6, f2mul(n0, X.x7));
    C[6] = f2fma(X.x1, X.x5, f2mul(n2, X.x4));
    C[7] = f2fma(X.x2, X.x3, f2mul(n0, X.x5));
    C[8] = f2fma(X.x0, X.x4, f2mul(n1, X.x3));
    det  = f2fma(X.x0, C[0], f2fma(X.x1, C[1], f2mul(X.x2, C[2])));
}

__device__ __forceinline__ void apply(P2& X, const u64 C[9], u64 hg, u64 rr) {
    X.x0 = f2fma(rr, C[0], f2mul(hg, X.x0));
    X.x1 = f2fma(rr, C[1], f2mul(hg, X.x1));
    X.x2 = f2fma(rr, C[2], f2mul(hg, X.x2));
    X.x3 = f2fma(rr, C[3], f2mul(hg, X.x3));
    X.x4 = f2fma(rr, C[4], f2mul(hg, X.x4));
    X.x5 = f2fma(rr, C[5], f2mul(hg, X.x5));
    X.x6 = f2fma(rr, C[6], f2mul(hg, X.x6));
    X.x7 = f2fma(rr, C[7], f2mul(hg, X.x7));
    X.x8 = f2fma(rr, C[8], f2mul(hg, X.x8));
}

// Head step: det-scaled Newton with cheap 1-polish g.
__device__ __forceinline__ void step_scaled(P2& X) {
    u64 C[9], det;
    cof_det(X, C, det);
    float dl, dh;
    f2unpack(det, dl, dh);
    const float gl = invcbrt1(fmaxf(fabsf(dl), 1e-30f));
    const float gh = invcbrt1(fmaxf(fabsf(dh), 1e-30f));
    const float rl = copysignf(0.5f * gl * gl, dl);
    const float rh = copysignf(0.5f * gh * gh, dh);
    apply(X, C, f2pack(0.5f * gl, 0.5f * gh), f2pack(rl, rh));
}

__global__ void __launch_bounds__(TPB)
polar_w3_kernel(const float* __restrict__ rot,
                const float* __restrict__ mat,
                float* __restrict__ out,
                float* __restrict__ logdet,
                int N)
{
    __shared__ float s[TPB * 18];
    const int tid  = threadIdx.x;
    const int base = blockIdx.x * (TPB * 2);
    const int nmat = min(TPB * 2, N - base);
    const int nflt = nmat * 9;

    // ---- cooperative coalesced load: global -> smem (one warp) ----
    {
        const float* g = rot + (size_t)base * 9;
        const int nv = nflt >> 2;
        const float4* g4 = reinterpret_cast<const float4*>(g);
        float4* s4 = reinterpret_cast<float4*>(s);
        for (int i = tid; i < nv; i += TPB) s4[i] = g4[i];
        for (int i = (nv << 2) + tid; i < nflt; i += TPB) s[i] = g[i];
    }

    const float m0 = __ldg(mat + 0), m1 = __ldg(mat + 1), m2 = __ldg(mat + 2);
    const float m3 = __ldg(mat + 3), m4 = __ldg(mat + 4), m5 = __ldg(mat + 5);
    const float m6 = __ldg(mat + 6), m7 = __ldg(mat + 7), m8 = __ldg(mat + 8);
    __syncwarp();

    const bool vlo = (base + 2 * tid)     < N;
    const bool vhi = (base + 2 * tid + 1) < N;

    u64 R[9];
    {
        const int olo = 2 * tid * 9, ohi = olo + 9;
        #pragma unroll
        for (int k = 0; k < 9; ++k) {
            const float idv = (k == 0 || k == 4 || k == 8) ? 1.0f : 0.0f;
            const float a = vlo ? s[olo + k] : idv;
            const float b = vhi ? s[ohi + k] : idv;
            R[k] = f2pack(a, b);
        }
    }
    __syncwarp();

    const u64 M0 = f2pack(m0, m0), M1 = f2pack(m1, m1), M2 = f2pack(m2, m2);
    const u64 M3 = f2pack(m3, m3), M4 = f2pack(m4, m4), M5 = f2pack(m5, m5);
    const u64 M6 = f2pack(m6, m6), M7 = f2pack(m7, m7), M8 = f2pack(m8, m8);

    P2 X;
    X.x0 = f2fma(R[0], M0, f2fma(R[1], M3, f2mul(R[2], M6)));
    X.x1 = f2fma(R[0], M1, f2fma(R[1], M4, f2mul(R[2], M7)));
    X.x2 = f2fma(R[0], M2, f2fma(R[1], M5, f2mul(R[2], M8)));
    X.x3 = f2fma(R[3], M0, f2fma(R[4], M3, f2mul(R[5], M6)));
    X.x4 = f2fma(R[3], M1, f2fma(R[4], M4, f2mul(R[5], M7)));
    X.x5 = f2fma(R[3], M2, f2fma(R[4], M5, f2mul(R[5], M8)));
    X.x6 = f2fma(R[6], M0, f2fma(R[7], M3, f2mul(R[8], M6)));
    X.x7 = f2fma(R[6], M1, f2fma(R[7], M4, f2mul(R[8], M7)));
    X.x8 = f2fma(R[6], M2, f2fma(R[7], M5, f2mul(R[8], M8)));

    // ---- head: 4 unrolled det-scaled steps, zero votes ----
    #pragma unroll
    for (int it = 0; it < 4; ++it) step_scaled(X);

    // ---- tail: plain Newton with PRE-step exit test (free) ----
    #pragma unroll 1
    for (int it = 0; it < 8; ++it) {
        u64 C[9], det;
        cof_det(X, C, det);
        float dl, dh;
        f2unpack(det, dl, dh);
        const bool ok = (fabsf(fabsf(dl) - 1.0f) < 2e-4f) &&
                        (fabsf(fabsf(dh) - 1.0f) < 2e-4f);
        if (__all_sync(0xffffffffu, ok)) break;   // exit WITHOUT applying
        const float rl = 0.5f * rcp_fast(dl);
        const float rh = 0.5f * rcp_fast(dh);
        apply(X, C, 0x3F0000003F000000ULL /*(0.5f,0.5f)*/, f2pack(rl, rh));
    }

    // ---- scatter to smem, cooperative coalesced store ----
    {
        const int olo = 2 * tid * 9, ohi = olo + 9;
        float a, b;
        f2unpack(X.x0, a, b); s[olo + 0] = a; s[ohi + 0] = b;
        f2unpack(X.x1, a, b); s[olo + 1] = a; s[ohi + 1] = b;
        f2unpack(X.x2, a, b); s[olo + 2] = a; s[ohi + 2] = b;
        f2unpack(X.x3, a, b); s[olo + 3] = a; s[ohi + 3] = b;
        f2unpack(X.x4, a, b); s[olo + 4] = a; s[ohi + 4] = b;
        f2unpack(X.x5, a, b); s[olo + 5] = a; s[ohi + 5] = b;
        f2unpack(X.x6, a, b); s[olo + 6] = a; s[ohi + 6] = b;
        f2unpack(X.x7, a, b); s[olo + 7] = a; s[ohi + 7] = b;
        f2unpack(X.x8, a, b); s[olo + 8] = a; s[ohi + 8] = b;
    }
    __syncwarp();
    {
        float* g = out + (size_t)base * 9;
        const int nv = nflt >> 2;
        const float4* s4 = reinterpret_cast<const float4*>(s);
        float4* g4 = reinterpret_cast<float4*>(g);
        for (int i = tid; i < nv; i += TPB) g4[i] = s4[i];
        for (int i = (nv << 2) + tid; i < nflt; i += TPB) g[i] = s[i];
    }

    for (int i = tid; i < nmat; i += TPB) logdet[base + i] = 0.0f;
}

__global__ void zero_tail_kernel(float* __restrict__ p, long long n)
{
    long long i = (long long)blockIdx.x * blockDim.x + threadIdx.x;
    if (i < n) p[i] = 0.0f;
}

extern "C" void kernel_launch(void* const* d_in, const int* in_sizes, int n_in,
                              void* d_out, int out_size)
{
    const float* rot = (const float*)d_in[0];
    const float* mat = (const float*)d_in[1];
    float* out = (float*)d_out;

    const int N = in_sizes[0] / 9;
    float* logdet = out + (size_t)N * 9;

    const int mats_per_block = TPB * 2;
    const int blocks = (N + mats_per_block - 1) / mats_per_block;
    polar_w3_kernel<<<blocks, TPB>>>(rot, mat, out, logdet, N);

    const long long used = 10LL * N;
    if ((long long)out_size > used) {
        const long long extra = (long long)out_size - used;
        const int zb = (int)((extra + 255) / 256);
        zero_tail_kernel<<<zb, 256>>>(out + used, extra);
    }
}

// round 15
// speedup vs baseline: 1.2076x; 1.2076x over previous
#include <cuda_runtime.h>

// Polar decomposition of A = rotation[n] @ mat. One warp per CTA (TPB=32).
// R13 base (best: 31.8us) + full-tile fast-path kernel (no predication, no
// staging-loop overhead) + looser test-after-step tol (2.5e-2 -> worst output
// element error ~3e-4, inside the 1e-3 budget).
//  head: 3 det-scaled Newton steps (g via bit trick + 1 FMA polish).
//  tail: plain Newton X <- 0.5*X + (0.5/det)*cof(X); exit when |det(X_in)|
//        within 2.5e-2 of 1, tested AFTER the step (quadratic polish).

#define TPB 32
typedef unsigned long long u64;

__device__ __forceinline__ u64 f2pack(float lo, float hi) {
    u64 r; asm("mov.b64 %0, {%1, %2};" : "=l"(r) : "f"(lo), "f"(hi)); return r;
}
__device__ __forceinline__ void f2unpack(u64 v, float& lo, float& hi) {
    asm("mov.b64 {%0, %1}, %2;" : "=f"(lo), "=f"(hi) : "l"(v));
}
__device__ __forceinline__ u64 f2mul(u64 a, u64 b) {
    u64 d; asm("mul.rn.f32x2 %0, %1, %2;" : "=l"(d) : "l"(a), "l"(b)); return d;
}
__device__ __forceinline__ u64 f2fma(u64 a, u64 b, u64 c) {
    u64 d; asm("fma.rn.f32x2 %0, %1, %2, %3;" : "=l"(d) : "l"(a), "l"(b), "l"(c)); return d;
}
__device__ __forceinline__ u64 f2neg(u64 a) { return a ^ 0x8000000080000000ULL; }
__device__ __forceinline__ float rcp_fast(float x) {
    float r; asm("rcp.approx.f32 %0, %1;" : "=f"(r) : "f"(x)); return r;
}

// |x|^(-1/3): bit trick + 1 FMA polish (~2e-3, fine for preconditioning).
__device__ __forceinline__ float invcbrt1(float x) {
    int i = __float_as_int(x);
    i = 0x54A2FA8C - i / 3;
    float y = __int_as_float(i);
    const float y3 = y * y * y;
    return y * 0.33333333f * fmaf(-x, y3, 4.0f);
}

struct P2 { u64 x0,x1,x2,x3,x4,x5,x6,x7,x8; };

__device__ __forceinline__ void cof_det(const P2& X, u64 C[9], u64& det) {
    const u64 n0 = f2neg(X.x0), n1 = f2neg(X.x1), n2 = f2neg(X.x2);
    const u64 n3 = f2neg(X.x3), n4 = f2neg(X.x4), n5 = f2neg(X.x5);
    C[0] = f2fma(X.x4, X.x8, f2mul(n5, X.x7));
    C[1] = f2fma(X.x5, X.x6, f2mul(n3, X.x8));
    C[2] = f2fma(X.x3, X.x7, f2mul(n4, X.x6));
    C[3] = f2fma(X.x2, X.x7, f2mul(n1, X.x8));
    C[4] = f2fma(X.x0, X.x8, f2mul(n2, X.x6));
    C[5] = f2fma(X.x1, X.x6, f2mul(n0, X.x7));
    C[6] = f2fma(X.x1, X.x5, f2mul(n2, X.x4));
    C[7] = f2fma(X.x2, X.x3, f2mul(n0, X.x5));
    C[8] = f2fma(X.x0, X.x4, f2mul(n1, X.x3));
    det  = f2fma(X.x0, C[0], f2fma(X.x1, C[1], f2mul(X.x2, C[2])));
}

__device__ __forceinline__ void apply(P2& X, const u64 C[9], u64 hg, u64 rr) {
    X.x0 = f2fma(rr, C[0], f2mul(hg, X.x0));
    X.x1 = f2fma(rr, C[1], f2mul(hg, X.x1));
    X.x2 = f2fma(rr, C[2], f2mul(hg, X.x2));
    X.x3 = f2fma(rr, C[3], f2mul(hg, X.x3));
    X.x4 = f2fma(rr, C[4], f2mul(hg, X.x4));
    X.x5 = f2fma(rr, C[5], f2mul(hg, X.x5));
    X.x6 = f2fma(rr, C[6], f2mul(hg, X.x6));
    X.x7 = f2fma(rr, C[7], f2mul(hg, X.x7));
    X.x8 = f2fma(rr, C[8], f2mul(hg, X.x8));
}

__device__ __forceinline__ void step_scaled(P2& X) {
    u64 C[9], det;
    cof_det(X, C, det);
    float dl, dh;
    f2unpack(det, dl, dh);
    const float gl = invcbrt1(fmaxf(fabsf(dl), 1e-30f));
    const float gh = invcbrt1(fmaxf(fabsf(dh), 1e-30f));
    const float rl = copysignf(0.5f * gl * gl, dl);
    const float rh = copysignf(0.5f * gh * gh, dh);
    apply(X, C, f2pack(0.5f * gl, 0.5f * gh), f2pack(rl, rh));
}

// Plain Newton; true iff |det(X_in)| within 2.5e-2 of 1 (the step just
// performed squares the error -> worst accepted output err ~3e-4).
__device__ __forceinline__ bool step_plain(P2& X) {
    u64 C[9], det;
    cof_det(X, C, det);
    float dl, dh;
    f2unpack(det, dl, dh);
    const float rl = 0.5f * rcp_fast(dl);
    const float rh = 0.5f * rcp_fast(dh);
    apply(X, C, 0x3F0000003F000000ULL /*(0.5f,0.5f)*/, f2pack(rl, rh));
    return (fabsf(fabsf(dl) - 1.0f) < 2.5e-2f) &&
           (fabsf(fabsf(dh) - 1.0f) < 2.5e-2f);
}

__device__ __forceinline__ void iterate(P2& X) {
    #pragma unroll
    for (int it = 0; it < 3; ++it) step_scaled(X);
    #pragma unroll 1
    for (int it = 0; it < 9; ++it) {
        const bool ok = step_plain(X);
        if (__all_sync(0xffffffffu, ok)) break;
    }
}

__device__ __forceinline__ void init_matmul(P2& X, const u64 R[9], const float* mat) {
    u64 M[9];
    #pragma unroll
    for (int k = 0; k < 9; ++k) { const float m = __ldg(mat + k); M[k] = f2pack(m, m); }
    X.x0 = f2fma(R[0], M[0], f2fma(R[1], M[3], f2mul(R[2], M[6])));
    X.x1 = f2fma(R[0], M[1], f2fma(R[1], M[4], f2mul(R[2], M[7])));
    X.x2 = f2fma(R[0], M[2], f2fma(R[1], M[5], f2mul(R[2], M[8])));
    X.x3 = f2fma(R[3], M[0], f2fma(R[4], M[3], f2mul(R[5], M[6])));
    X.x4 = f2fma(R[3], M[1], f2fma(R[4], M[4], f2mul(R[5], M[7])));
    X.x5 = f2fma(R[3], M[2], f2fma(R[4], M[5], f2mul(R[5], M[8])));
    X.x6 = f2fma(R[6], M[0], f2fma(R[7], M[3], f2mul(R[8], M[6])));
    X.x7 = f2fma(R[6], M[1], f2fma(R[7], M[4], f2mul(R[8], M[7])));
    X.x8 = f2fma(R[6], M[2], f2fma(R[7], M[5], f2mul(R[8], M[8])));
}

// ---- HOT kernel: full 64-matrix tiles only, zero predication ----
__global__ void __launch_bounds__(TPB)
polar_full_kernel(const float* __restrict__ rot,
                  const float* __restrict__ mat,
                  float* __restrict__ out,
                  float* __restrict__ logdet)
{
    __shared__ float s[TPB * 18];                  // 576 floats = 144 float4
    const int tid  = threadIdx.x;
    const int base = blockIdx.x * (TPB * 2);

    // coalesced load: 4 full rounds + 16-thread round, no loop overhead
    {
        const float4* g4 = reinterpret_cast<const float4*>(rot + (size_t)base * 9);
        float4* s4 = reinterpret_cast<float4*>(s);
        #pragma unroll
        for (int j = 0; j < 4; ++j) s4[tid + 32 * j] = g4[tid + 32 * j];
        if (tid < 16) s4[128 + tid] = g4[128 + tid];
    }
    __syncwarp();

    const int olo = 2 * tid * 9, ohi = olo + 9;
    u64 R[9];
    #pragma unroll
    for (int k = 0; k < 9; ++k) R[k] = f2pack(s[olo + k], s[ohi + k]);
    __syncwarp();

    P2 X;
    init_matmul(X, R, mat);
    iterate(X);

    // scatter to smem, coalesced store
    {
        float a, b;
        f2unpack(X.x0, a, b); s[olo + 0] = a; s[ohi + 0] = b;
        f2unpack(X.x1, a, b); s[olo + 1] = a; s[ohi + 1] = b;
        f2unpack(X.x2, a, b); s[olo + 2] = a; s[ohi + 2] = b;
        f2unpack(X.x3, a, b); s[olo + 3] = a; s[ohi + 3] = b;
        f2unpack(X.x4, a, b); s[olo + 4] = a; s[ohi + 4] = b;
        f2unpack(X.x5, a, b); s[olo + 5] = a; s[ohi + 5] = b;
        f2unpack(X.x6, a, b); s[olo + 6] = a; s[ohi + 6] = b;
        f2unpack(X.x7, a, b); s[olo + 7] = a; s[ohi + 7] = b;
        f2unpack(X.x8, a, b); s[olo + 8] = a; s[ohi + 8] = b;
    }
    __syncwarp();
    {
        float4* g4 = reinterpret_cast<float4*>(out + (size_t)base * 9);
        const float4* s4 = reinterpret_cast<const float4*>(s);
        #pragma unroll
        for (int j = 0; j < 4; ++j) g4[tid + 32 * j] = s4[tid + 32 * j];
        if (tid < 16) g4[128 + tid] = s4[128 + tid];
    }
    *reinterpret_cast<float2*>(logdet + base + 2 * tid) = make_float2(0.f, 0.f);
}

// ---- generic kernel: handles the (possibly empty) remainder tile ----
__global__ void __launch_bounds__(TPB)
polar_rem_kernel(const float* __restrict__ rot,
                 const float* __restrict__ mat,
                 float* __restrict__ out,
                 float* __restrict__ logdet,
                 int start, int N)
{
    __shared__ float s[TPB * 18];
    const int tid  = threadIdx.x;
    const int base = start;
    const int nmat = N - base;
    const int nflt = nmat * 9;

    {
        const float* g = rot + (size_t)base * 9;
        const int nv = nflt >> 2;
        const float4* g4 = reinterpret_cast<const float4*>(g);
        float4* s4 = reinterpret_cast<float4*>(s);
        for (int i = tid; i < nv; i += TPB) s4[i] = g4[i];
        for (int i = (nv << 2) + tid; i < nflt; i += TPB) s[i] = g[i];
    }
    __syncwarp();

    const bool vlo = (base + 2 * tid)     < N;
    const bool vhi = (base + 2 * tid + 1) < N;
    const int olo = 2 * tid * 9, ohi = olo + 9;
    u64 R[9];
    #pragma unroll
    for (int k = 0; k < 9; ++k) {
        const float idv = (k == 0 || k == 4 || k == 8) ? 1.0f : 0.0f;
        R[k] = f2pack(vlo ? s[olo + k] : idv, vhi ? s[ohi + k] : idv);
    }
    __syncwarp();

    P2 X;
    init_matmul(X, R, mat);
    iterate(X);

    {
        float a, b;
        f2unpack(X.x0, a, b); s[olo + 0] = a; s[ohi + 0] = b;
        f2unpack(X.x1, a, b); s[olo + 1] = a; s[ohi + 1] = b;
        f2unpack(X.x2, a, b); s[olo + 2] = a; s[ohi + 2] = b;
        f2unpack(X.x3, a, b); s[olo + 3] = a; s[ohi + 3] = b;
        f2unpack(X.x4, a, b); s[olo + 4] = a; s[ohi + 4] = b;
        f2unpack(X.x5, a, b); s[olo + 5] = a; s[ohi + 5] = b;
        f2unpack(X.x6, a, b); s[olo + 6] = a; s[ohi + 6] = b;
        f2unpack(X.x7, a, b); s[olo + 7] = a; s[ohi + 7] = b;
        f2unpack(X.x8, a, b); s[olo + 8] = a; s[ohi + 8] = b;
    }
    __syncwarp();
    {
        float* g = out + (size_t)base * 9;
        const int nv = nflt >> 2;
        const float4* s4 = reinterpret_cast<const float4*>(s);
        float4* g4 = reinterpret_cast<float4*>(g);
        for (int i = tid; i < nv; i += TPB) g4[i] = s4[i];
        for (int i = (nv << 2) + tid; i < nflt; i += TPB) g[i] = s[i];
    }
    for (int i = tid; i < nmat; i += TPB) logdet[base + i] = 0.0f;
}

__global__ void zero_tail_kernel(float* __restrict__ p, long long n)
{
    long long i = (long long)blockIdx.x * blockDim.x + threadIdx.x;
    if (i < n) p[i] = 0.0f;
}

extern "C" void kernel_launch(void* const* d_in, const int* in_sizes, int n_in,
                              void* d_out, int out_size)
{
    const float* rot = (const float*)d_in[0];
    const float* mat = (const float*)d_in[1];
    float* out = (float*)d_out;

    const int N = in_sizes[0] / 9;
    float* logdet = out + (size_t)N * 9;

    const int full_blocks = N / (TPB * 2);
    if (full_blocks > 0)
        polar_full_kernel<<<full_blocks, TPB>>>(rot, mat, out, logdet);
    const int rem_start = full_blocks * (TPB * 2);
    if (rem_start < N)
        polar_rem_kernel<<<1, TPB>>>(rot, mat, out, logdet, rem_start, N);

    const long long used = 10LL * N;
    if ((long long)out_size > used) {
        const long long extra = (long long)out_size - used;
        const int zb = (int)((extra + 255) / 256);
        zero_tail_kernel<<<zb, 256>>>(out + used, extra);
    }
}

// round 16
// speedup vs baseline: 1.3117x; 1.0862x over previous
#include <cuda_runtime.h>

// Polar decomposition of A = rotation[n] @ mat. One warp per CTA (TPB=32),
// full-tile fast path (R15 base, 27.8us).
//  head: 3 det-scaled Newton steps; g = |det|^(-1/3) via raw bit trick on
//        steps 1-2 (preconditioning only) + 1 FMA polish on step 3 (whose g
//        accuracy sets det entering the tested tail).
//  tail: plain Newton X <- 0.5*X + (0.5/det)*cof(X); exit when |det(X_in)|
//        within 2.5e-2 of 1 tested AFTER the step (quadratic polish).
// Cofactors use sub.rn.f32x2 (mul+mul+sub): no XOR-negs -> alu pipe unloaded.

#define TPB 32
typedef unsigned long long u64;

__device__ __forceinline__ u64 f2pack(float lo, float hi) {
    u64 r; asm("mov.b64 %0, {%1, %2};" : "=l"(r) : "f"(lo), "f"(hi)); return r;
}
__device__ __forceinline__ void f2unpack(u64 v, float& lo, float& hi) {
    asm("mov.b64 {%0, %1}, %2;" : "=f"(lo), "=f"(hi) : "l"(v));
}
__device__ __forceinline__ u64 f2mul(u64 a, u64 b) {
    u64 d; asm("mul.rn.f32x2 %0, %1, %2;" : "=l"(d) : "l"(a), "l"(b)); return d;
}
__device__ __forceinline__ u64 f2sub(u64 a, u64 b) {
    u64 d; asm("sub.rn.f32x2 %0, %1, %2;" : "=l"(d) : "l"(a), "l"(b)); return d;
}
__device__ __forceinline__ u64 f2fma(u64 a, u64 b, u64 c) {
    u64 d; asm("fma.rn.f32x2 %0, %1, %2, %3;" : "=l"(d) : "l"(a), "l"(b), "l"(c)); return d;
}
__device__ __forceinline__ float rcp_fast(float x) {
    float r; asm("rcp.approx.f32 %0, %1;" : "=f"(r) : "f"(x)); return r;
}

// |x|^(-1/3) raw bit trick (~3% - fine for pure preconditioning).
__device__ __forceinline__ float invcbrt0(float x) {
    int i = __float_as_int(x);
    i = 0x54A2FA8C - i / 3;
    return __int_as_float(i);
}
// + one FMA polish (~2e-3) - for the last head step.
__device__ __forceinline__ float invcbrt1(float x) {
    float y = invcbrt0(x);
    const float y3 = y * y * y;
    return y * 0.33333333f * fmaf(-x, y3, 4.0f);
}

struct P2 { u64 x0,x1,x2,x3,x4,x5,x6,x7,x8; };

// Cofactors + det via packed sub (no negations).
__device__ __forceinline__ void cof_det(const P2& X, u64 C[9], u64& det) {
    C[0] = f2sub(f2mul(X.x4, X.x8), f2mul(X.x5, X.x7));
    C[1] = f2sub(f2mul(X.x5, X.x6), f2mul(X.x3, X.x8));
    C[2] = f2sub(f2mul(X.x3, X.x7), f2mul(X.x4, X.x6));
    C[3] = f2sub(f2mul(X.x2, X.x7), f2mul(X.x1, X.x8));
    C[4] = f2sub(f2mul(X.x0, X.x8), f2mul(X.x2, X.x6));
    C[5] = f2sub(f2mul(X.x1, X.x6), f2mul(X.x0, X.x7));
    C[6] = f2sub(f2mul(X.x1, X.x5), f2mul(X.x2, X.x4));
    C[7] = f2sub(f2mul(X.x2, X.x3), f2mul(X.x0, X.x5));
    C[8] = f2sub(f2mul(X.x0, X.x4), f2mul(X.x1, X.x3));
    det  = f2fma(X.x0, C[0], f2fma(X.x1, C[1], f2mul(X.x2, C[2])));
}

__device__ __forceinline__ void apply(P2& X, const u64 C[9], u64 hg, u64 rr) {
    X.x0 = f2fma(rr, C[0], f2mul(hg, X.x0));
    X.x1 = f2fma(rr, C[1], f2mul(hg, X.x1));
    X.x2 = f2fma(rr, C[2], f2mul(hg, X.x2));
    X.x3 = f2fma(rr, C[3], f2mul(hg, X.x3));
    X.x4 = f2fma(rr, C[4], f2mul(hg, X.x4));
    X.x5 = f2fma(rr, C[5], f2mul(hg, X.x5));
    X.x6 = f2fma(rr, C[6], f2mul(hg, X.x6));
    X.x7 = f2fma(rr, C[7], f2mul(hg, X.x7));
    X.x8 = f2fma(rr, C[8], f2mul(hg, X.x8));
}

template <bool POLISH>
__device__ __forceinline__ void step_scaled(P2& X) {
    u64 C[9], det;
    cof_det(X, C, det);
    float dl, dh;
    f2unpack(det, dl, dh);
    const float al = fmaxf(fabsf(dl), 1e-30f);
    const float ah = fmaxf(fabsf(dh), 1e-30f);
    const float gl = POLISH ? invcbrt1(al) : invcbrt0(al);
    const float gh = POLISH ? invcbrt1(ah) : invcbrt0(ah);
    const float rl = copysignf(0.5f * gl * gl, dl);
    const float rh = copysignf(0.5f * gh * gh, dh);
    apply(X, C, f2pack(0.5f * gl, 0.5f * gh), f2pack(rl, rh));
}

// Plain Newton; true iff |det(X_in)| within 2.5e-2 of 1 (the step just
// performed squares the error -> worst accepted output err ~3e-4).
__device__ __forceinline__ bool step_plain(P2& X) {
    u64 C[9], det;
    cof_det(X, C, det);
    float dl, dh;
    f2unpack(det, dl, dh);
    const float rl = 0.5f * rcp_fast(dl);
    const float rh = 0.5f * rcp_fast(dh);
    apply(X, C, 0x3F0000003F000000ULL /*(0.5f,0.5f)*/, f2pack(rl, rh));
    return (fabsf(fabsf(dl) - 1.0f) < 2.5e-2f) &&
           (fabsf(fabsf(dh) - 1.0f) < 2.5e-2f);
}

__device__ __forceinline__ void iterate(P2& X) {
    step_scaled<false>(X);
    step_scaled<false>(X);
    step_scaled<true>(X);
    #pragma unroll 1
    for (int it = 0; it < 9; ++it) {
        const bool ok = step_plain(X);
        if (__all_sync(0xffffffffu, ok)) break;
    }
}

__device__ __forceinline__ void init_matmul(P2& X, const u64 R[9], const float* mat) {
    u64 M[9];
    #pragma unroll
    for (int k = 0; k < 9; ++k) { const float m = __ldg(mat + k); M[k] = f2pack(m, m); }
    X.x0 = f2fma(R[0], M[0], f2fma(R[1], M[3], f2mul(R[2], M[6])));
    X.x1 = f2fma(R[0], M[1], f2fma(R[1], M[4], f2mul(R[2], M[7])));
    X.x2 = f2fma(R[0], M[2], f2fma(R[1], M[5], f2mul(R[2], M[8])));
    X.x3 = f2fma(R[3], M[0], f2fma(R[4], M[3], f2mul(R[5], M[6])));
    X.x4 = f2fma(R[3], M[1], f2fma(R[4], M[4], f2mul(R[5], M[7])));
    X.x5 = f2fma(R[3], M[2], f2fma(R[4], M[5], f2mul(R[5], M[8])));
    X.x6 = f2fma(R[6], M[0], f2fma(R[7], M[3], f2mul(R[8], M[6])));
    X.x7 = f2fma(R[6], M[1], f2fma(R[7], M[4], f2mul(R[8], M[7])));
    X.x8 = f2fma(R[6], M[2], f2fma(R[7], M[5], f2mul(R[8], M[8])));
}

// ---- HOT kernel: full 64-matrix tiles, zero predication ----
__global__ void __launch_bounds__(TPB)
polar_full_kernel(const float* __restrict__ rot,
                  const float* __restrict__ mat,
                  float* __restrict__ out,
                  float* __restrict__ logdet)
{
    __shared__ float s[TPB * 18];
    const int tid  = threadIdx.x;
    const int base = blockIdx.x * (TPB * 2);

    {
        const float4* g4 = reinterpret_cast<const float4*>(rot + (size_t)base * 9);
        float4* s4 = reinterpret_cast<float4*>(s);
        #pragma unroll
        for (int j = 0; j < 4; ++j) s4[tid + 32 * j] = g4[tid + 32 * j];
        if (tid < 16) s4[128 + tid] = g4[128 + tid];
    }
    __syncwarp();

    const int olo = 2 * tid * 9, ohi = olo + 9;
    u64 R[9];
    #pragma unroll
    for (int k = 0; k < 9; ++k) R[k] = f2pack(s[olo + k], s[ohi + k]);
    __syncwarp();

    P2 X;
    init_matmul(X, R, mat);
    iterate(X);

    {
        float a, b;
        f2unpack(X.x0, a, b); s[olo + 0] = a; s[ohi + 0] = b;
        f2unpack(X.x1, a, b); s[olo + 1] = a; s[ohi + 1] = b;
        f2unpack(X.x2, a, b); s[olo + 2] = a; s[ohi + 2] = b;
        f2unpack(X.x3, a, b); s[olo + 3] = a; s[ohi + 3] = b;
        f2unpack(X.x4, a, b); s[olo + 4] = a; s[ohi + 4] = b;
        f2unpack(X.x5, a, b); s[olo + 5] = a; s[ohi + 5] = b;
        f2unpack(X.x6, a, b); s[olo + 6] = a; s[ohi + 6] = b;
        f2unpack(X.x7, a, b); s[olo + 7] = a; s[ohi + 7] = b;
        f2unpack(X.x8, a, b); s[olo + 8] = a; s[ohi + 8] = b;
    }
    __syncwarp();
    {
        float4* g4 = reinterpret_cast<float4*>(out + (size_t)base * 9);
        const float4* s4 = reinterpret_cast<const float4*>(s);
        #pragma unroll
        for (int j = 0; j < 4; ++j) g4[tid + 32 * j] = s4[tid + 32 * j];
        if (tid < 16) g4[128 + tid] = s4[128 + tid];
    }
    *reinterpret_cast<float2*>(logdet + base + 2 * tid) = make_float2(0.f, 0.f);
}

// ---- generic kernel: handles the (possibly empty) remainder tile ----
__global__ void __launch_bounds__(TPB)
polar_rem_kernel(const float* __restrict__ rot,
                 const float* __restrict__ mat,
                 float* __restrict__ out,
                 float* __restrict__ logdet,
                 int start, int N)
{
    __shared__ float s[TPB * 18];
    const int tid  = threadIdx.x;
    const int base = start;
    const int nmat = N - base;
    const int nflt = nmat * 9;

    {
        const float* g = rot + (size_t)base * 9;
        const int nv = nflt >> 2;
        const float4* g4 = reinterpret_cast<const float4*>(g);
        float4* s4 = reinterpret_cast<float4*>(s);
        for (int i = tid; i < nv; i += TPB) s4[i] = g4[i];
        for (int i = (nv << 2) + tid; i < nflt; i += TPB) s[i] = g[i];
    }
    __syncwarp();

    const bool vlo = (base + 2 * tid)     < N;
    const bool vhi = (base + 2 * tid + 1) < N;
    const int olo = 2 * tid * 9, ohi = olo + 9;
    u64 R[9];
    #pragma unroll
    for (int k = 0; k < 9; ++k) {
        const float idv = (k == 0 || k == 4 || k == 8) ? 1.0f : 0.0f;
        R[k] = f2pack(vlo ? s[olo + k] : idv, vhi ? s[ohi + k] : idv);
    }
    __syncwarp();

    P2 X;
    init_matmul(X, R, mat);
    iterate(X);

    {
        float a, b;
        f2unpack(X.x0, a, b); s[olo + 0] = a; s[ohi + 0] = b;
        f2unpack(X.x1, a, b); s[olo + 1] = a; s[ohi + 1] = b;
        f2unpack(X.x2, a, b); s[olo + 2] = a; s[ohi + 2] = b;
        f2unpack(X.x3, a, b); s[olo + 3] = a; s[ohi + 3] = b;
        f2unpack(X.x4, a, b); s[olo + 4] = a; s[ohi + 4] = b;
        f2unpack(X.x5, a, b); s[olo + 5] = a; s[ohi + 5] = b;
        f2unpack(X.x6, a, b); s[olo + 6] = a; s[ohi + 6] = b;
        f2unpack(X.x7, a, b); s[olo + 7] = a; s[ohi + 7] = b;
        f2unpack(X.x8, a, b); s[olo + 8] = a; s[ohi + 8] = b;
    }
    __syncwarp();
    {
        float* g = out + (size_t)base * 9;
        const int nv = nflt >> 2;
        const float4* s4 = reinterpret_cast<const float4*>(s);
        float4* g4 = reinterpret_cast<float4*>(g);
        for (int i = tid; i < nv; i += TPB) g4[i] = s4[i];
        for (int i = (nv << 2) + tid; i < nflt; i += TPB) g[i] = s[i];
    }
    for (int i = tid; i < nmat; i += TPB) logdet[base + i] = 0.0f;
}

__global__ void zero_tail_kernel(float* __restrict__ p, long long n)
{
    long long i = (long long)blockIdx.x * blockDim.x + threadIdx.x;
    if (i < n) p[i] = 0.0f;
}

extern "C" void kernel_launch(void* const* d_in, const int* in_sizes, int n_in,
                              void* d_out, int out_size)
{
    const float* rot = (const float*)d_in[0];
    const float* mat = (const float*)d_in[1];
    float* out = (float*)d_out;

    const int N = in_sizes[0] / 9;
    float* logdet = out + (size_t)N * 9;

    const int full_blocks = N / (TPB * 2);
    if (full_blocks > 0)
        polar_full_kernel<<<full_blocks, TPB>>>(rot, mat, out, logdet);
    const int rem_start = full_blocks * (TPB * 2);
    if (rem_start < N)
        polar_rem_kernel<<<1, TPB>>>(rot, mat, out, logdet, rem_start, N);

    const long long used = 10LL * N;
    if ((long long)out_size > used) {
        const long long extra = (long long)out_size - used;
        const int zb = (int)((extra + 255) / 256);
        zero_tail_kernel<<<zb, 256>>>(out + used, extra);
    }
}